// round 7
// baseline (speedup 1.0000x reference)
#include <cuda_runtime.h>

#define NN 400
#define NC 1000
#define NB 10
#define NE 800
#define XND 121   // 85 cont + 4 shape emb + 32 op emb
#define CF 24
#define DH 128    // 2H
#define H 64
#define CT 128    // configs per tile (mlp)
#define PADW 132  // padded smem row stride for 128-wide tiles
#define CT64 64   // configs per tile (sage kernels)
#define PAD64 68  // padded smem row stride for 64-wide tiles

typedef unsigned long long ull_t;

// ---- scratch (module-load allocated, no cudaMalloc) ----
__device__ float g_bufA[(size_t)NN * NC * DH];  // 204.8 MB
__device__ float g_bufB[(size_t)NN * NC * DH];  // 204.8 MB
__device__ float g_base[NN * DH];
__device__ int   g_adj[NE];
__device__ int   g_off[NN + 1];
__device__ float g_invdeg[NN];
__device__ float g_invcnt[NB];

// ---- packed f32x2 helpers ----
__device__ __forceinline__ ull_t pk2(float x) {
    ull_t r; asm("mov.b64 %0, {%1, %1};" : "=l"(r) : "f"(x)); return r;
}
__device__ __forceinline__ ull_t fma2(ull_t a, ull_t b, ull_t c) {
    ull_t d; asm("fma.rn.f32x2 %0, %1, %2, %3;" : "=l"(d) : "l"(a), "l"(b), "l"(c)); return d;
}
__device__ __forceinline__ void upk(ull_t a, float& lo, float& hi) {
    asm("mov.b64 {%0, %1}, %2;" : "=f"(lo), "=f"(hi) : "l"(a));
}

// ============================================================
// Register-tiled GEMM core: tile = 128 features x CW configs.
// REQUIRES blockDim == 32*(CW/8). Thread tile: 4f x 8c.
// f0 = lane*4 (LDS.128 weights), c0 = warp*8 (broadcast x).
// xT: [D][PAD] (configs contiguous), ws: [D][128], bs128: [128]
// ============================================================
template<int D, int CW, int PAD, bool RELU>
__device__ __forceinline__ void gemm_core(const float* __restrict__ xT,
                                          const float* __restrict__ ws,
                                          const float* __restrict__ bs128,
                                          float* __restrict__ outg, int span) {
    const int t  = threadIdx.x;
    const int f0 = (t & 31) * 4;
    const int c0 = (t >> 5) * 8;

    ull_t acc[4][4];
    {
        float4 bv = *(const float4*)(bs128 + f0);
        ull_t b0 = pk2(bv.x), b1 = pk2(bv.y), b2_ = pk2(bv.z), b3 = pk2(bv.w);
        #pragma unroll
        for (int p = 0; p < 4; p++) { acc[0][p] = b0; acc[1][p] = b1; acc[2][p] = b2_; acc[3][p] = b3; }
    }

    #pragma unroll 4
    for (int k = 0; k < D; k++) {
        float4 wv = *(const float4*)(ws + k * DH + f0);
        ull_t w0 = pk2(wv.x), w1 = pk2(wv.y), w2 = pk2(wv.z), w3 = pk2(wv.w);
        const ulonglong2* xr = (const ulonglong2*)(xT + k * PAD + c0);
        ulonglong2 xA = xr[0], xB = xr[1];
        acc[0][0] = fma2(xA.x, w0, acc[0][0]);
        acc[1][0] = fma2(xA.x, w1, acc[1][0]);
        acc[2][0] = fma2(xA.x, w2, acc[2][0]);
        acc[3][0] = fma2(xA.x, w3, acc[3][0]);
        acc[0][1] = fma2(xA.y, w0, acc[0][1]);
        acc[1][1] = fma2(xA.y, w1, acc[1][1]);
        acc[2][1] = fma2(xA.y, w2, acc[2][1]);
        acc[3][1] = fma2(xA.y, w3, acc[3][1]);
        acc[0][2] = fma2(xB.x, w0, acc[0][2]);
        acc[1][2] = fma2(xB.x, w1, acc[1][2]);
        acc[2][2] = fma2(xB.x, w2, acc[2][2]);
        acc[3][2] = fma2(xB.x, w3, acc[3][2]);
        acc[0][3] = fma2(xB.y, w0, acc[0][3]);
        acc[1][3] = fma2(xB.y, w1, acc[1][3]);
        acc[2][3] = fma2(xB.y, w2, acc[2][3]);
        acc[3][3] = fma2(xB.y, w3, acc[3][3]);
    }

    #pragma unroll
    for (int p = 0; p < 4; p++) {
        int c = c0 + 2 * p;
        float lo0, hi0, lo1, hi1, lo2, hi2, lo3, hi3;
        upk(acc[0][p], lo0, hi0); upk(acc[1][p], lo1, hi1);
        upk(acc[2][p], lo2, hi2); upk(acc[3][p], lo3, hi3);
        if (RELU) {
            lo0 = fmaxf(lo0, 0.f); hi0 = fmaxf(hi0, 0.f);
            lo1 = fmaxf(lo1, 0.f); hi1 = fmaxf(hi1, 0.f);
            lo2 = fmaxf(lo2, 0.f); hi2 = fmaxf(hi2, 0.f);
            lo3 = fmaxf(lo3, 0.f); hi3 = fmaxf(hi3, 0.f);
        }
        if (c < span)     *(float4*)(outg + (size_t)c * DH + f0)       = make_float4(lo0, lo1, lo2, lo3);
        if (c + 1 < span) *(float4*)(outg + (size_t)(c + 1) * DH + f0) = make_float4(hi0, hi1, hi2, hi3);
    }
}

// ============================================================
// Setup: CSR by dst, degrees, per-graph node counts. One block.
// ============================================================
__global__ void k_prep(const int* __restrict__ ei, const int* __restrict__ batch) {
    __shared__ int cnt[NN];
    __shared__ int off[NN + 1];
    __shared__ int cur[NN];
    __shared__ int bc[NB];
    int t = threadIdx.x;
    for (int i = t; i < NN; i += blockDim.x) cnt[i] = 0;
    if (t < NB) bc[t] = 0;
    __syncthreads();
    for (int e = t; e < NE; e += blockDim.x) atomicAdd(&cnt[ei[NE + e]], 1);
    for (int i = t; i < NN; i += blockDim.x) atomicAdd(&bc[batch[i]], 1);
    __syncthreads();
    if (t == 0) {
        int s = 0;
        for (int i = 0; i < NN; i++) { off[i] = s; s += cnt[i]; }
        off[NN] = s;
    }
    __syncthreads();
    for (int i = t; i < NN; i += blockDim.x) {
        cur[i] = off[i];
        g_off[i] = off[i];
        g_invdeg[i] = 1.f / fmaxf((float)cnt[i], 1.f);
    }
    if (t == 0) g_off[NN] = off[NN];
    if (t < NB) g_invcnt[t] = 1.f / fmaxf((float)bc[t], 1.f);
    __syncthreads();
    for (int e = t; e < NE; e += blockDim.x) {
        int d = ei[NE + e];
        int p = atomicAdd(&cur[d], 1);
        g_adj[p] = ei[e];
    }
}

// ============================================================
// Per-node config-invariant part of layer 1:
// base[n][f] = b1[f] + xn[n] @ W1[0:121]
// ============================================================
__global__ void k_base(const float* __restrict__ node_feat, const int* __restrict__ opcode,
                       const float* __restrict__ op_emb, const float* __restrict__ shape_emb,
                       const float* __restrict__ W1, const float* __restrict__ b1) {
    __shared__ float xns[XND];
    int n = blockIdx.x, t = threadIdx.x;
    if (t < XND) {
        float v;
        if (t < 85) v = node_feat[n * 86 + t];
        else if (t < 89) { int st = (int)node_feat[n * 86 + 85]; v = shape_emb[st * 4 + (t - 85)]; }
        else v = op_emb[opcode[n] * 32 + (t - 89)];
        xns[t] = v;
    }
    __syncthreads();
    float acc = b1[t];
    #pragma unroll 11
    for (int k = 0; k < XND; k++) acc += xns[k] * W1[k * DH + t];
    g_base[n * DH + t] = acc;
}

// ============================================================
// Fused MLP: x1 = relu(base + cfg @ W1[121:145]); x2 = relu(x1 @ W2 + b2)
// -> g_bufA [n][c][128].  512 threads, 128c tile.
// ============================================================
__global__ void __launch_bounds__(512, 1)
k_mlp(const float* __restrict__ cfgf, const int* __restrict__ batch,
      const float* __restrict__ W1, const float* __restrict__ W2, const float* __restrict__ b2) {
    extern __shared__ float sm[];
    float* sb   = sm;                   // 128 (base)
    float* b2s  = sm + DH;              // 128
    float* w1t  = b2s + DH;             // 24*128
    float* cfgT = w1t + CF * DH;        // 24*132 (transposed [j][c])
    float* x1T  = cfgT + CF * PADW;     // 128*132 (transposed [k][c])
    float* w2s  = x1T + DH * PADW;      // 128*128

    const int n = blockIdx.y;
    const int c0b = blockIdx.x * CT;
    const int span = min(CT, NC - c0b);
    const int t = threadIdx.x;

    if (t < DH) { sb[t] = g_base[n * DH + t]; b2s[t] = b2[t]; }
    for (int e = t; e < CF * DH; e += 512) w1t[e] = W1[XND * DH + e];
    for (int e = t; e < DH * DH; e += 512) w2s[e] = W2[e];
    const int bn = batch[n];
    const float* cb_ = cfgf + ((size_t)bn * NC + c0b) * CF;
    for (int e = t; e < CF * CT; e += 512) {
        int c = e / CF, j = e - c * CF;
        cfgT[j * PADW + c] = (c < span) ? cb_[e] : 0.f;
    }
    __syncthreads();

    // Stage 1: 24-deep GEMM, store transposed to smem
    {
        const int f = t & 127, g = t >> 7;  // g in 0..3
        const ull_t bb1 = pk2(sb[f]);
        #pragma unroll
        for (int p0 = g * 4; p0 < 64; p0 += 16) {
            ull_t a0 = bb1, a1 = bb1, a2 = bb1, a3 = bb1;
            const int cb = 2 * p0;
            #pragma unroll
            for (int j = 0; j < CF; j++) {
                ull_t w = pk2(w1t[j * DH + f]);
                const ulonglong2* xr = (const ulonglong2*)(cfgT + j * PADW + cb);
                ulonglong2 xA = xr[0], xB = xr[1];
                a0 = fma2(xA.x, w, a0); a1 = fma2(xA.y, w, a1);
                a2 = fma2(xB.x, w, a2); a3 = fma2(xB.y, w, a3);
            }
            float lo, hi;
            float* xrow = x1T + f * PADW + cb;
            upk(a0, lo, hi); xrow[0] = fmaxf(lo, 0.f); xrow[1] = fmaxf(hi, 0.f);
            upk(a1, lo, hi); xrow[2] = fmaxf(lo, 0.f); xrow[3] = fmaxf(hi, 0.f);
            upk(a2, lo, hi); xrow[4] = fmaxf(lo, 0.f); xrow[5] = fmaxf(hi, 0.f);
            upk(a3, lo, hi); xrow[6] = fmaxf(lo, 0.f); xrow[7] = fmaxf(hi, 0.f);
        }
    }
    __syncthreads();

    // Stage 2: 128-deep register-tiled GEMM -> global (512 thr = 16 warps = 128c)
    float* outg = g_bufA + ((size_t)n * NC + c0b) * DH;
    gemm_core<DH, CT, PADW, true>(x1T, w2s, b2s, outg, span);
}

// ============================================================
// SAGE projection layer 0 (D=128 input): 256 threads, 64c tile,
// 2 CTAs/SM (fill of one overlaps compute of the other).
// Reads g_bufA, writes g_bufB [n][c][128] = (Wl·x+bg | Wr·x).
// ============================================================
__global__ void __launch_bounds__(256, 2)
k_sageG128(const float* __restrict__ Wl, const float* __restrict__ Wr, const float* __restrict__ bg) {
    extern __shared__ float sm[];
    float* xT = sm;                  // 128*PAD64
    float* ws = xT + 128 * PAD64;    // 128*128 (Wl | Wr interleaved on f)
    float* bs = ws + 128 * DH;       // 128 (bg | zeros)
    const int n = blockIdx.y, c0 = blockIdx.x * CT64;
    const int span = min(CT64, NC - c0);
    const int t = threadIdx.x;

    if (t < DH) bs[t] = (t < H) ? bg[t] : 0.f;
    for (int e = t; e < 128 * H; e += 256) {
        int k = e / H, f = e - k * H;
        ws[k * DH + f]     = Wl[e];
        ws[k * DH + H + f] = Wr[e];
    }
    const float* xb = g_bufA + ((size_t)n * NC + c0) * 128;
    for (int e = t; e < 128 * CT64; e += 256) {
        int c = e >> 7, k = e & 127;
        xT[k * PAD64 + c] = (c < span) ? xb[e] : 0.f;
    }
    __syncthreads();

    float* yb = g_bufB + ((size_t)n * NC + c0) * DH;
    gemm_core<128, CT64, PAD64, false>(xT, ws, bs, yb, span);
}

// ============================================================
// Fused SAGE layer (aggregate prev layer + project, D=64):
// x[k][c] = relu(in[n][c][k] + invdeg * sum_src in[src][c][64+k])
// then y = (x@Wl + bg | x@Wr) -> out.
// BtoA=true: in=g_bufB, out=g_bufA; else in=g_bufA, out=g_bufB.
// 256 threads, 64c tile (matches 8-warp gemm_core), 2 CTAs/SM.
// ============================================================
template<bool BtoA>
__global__ void __launch_bounds__(256, 2)
k_sageG64f(const float* __restrict__ Wl, const float* __restrict__ Wr, const float* __restrict__ bg) {
    extern __shared__ float sm[];
    float* xT = sm;                 // 64*PAD64
    float* ws = xT + 64 * PAD64;    // 64*128
    float* bs = ws + 64 * DH;       // 128
    const int n = blockIdx.y, c0 = blockIdx.x * CT64;
    const int span = min(CT64, NC - c0);
    const int t = threadIdx.x;
    const float* in  = BtoA ? g_bufB : g_bufA;
    float*       out = BtoA ? g_bufA : g_bufB;

    if (t < DH) bs[t] = (t < H) ? bg[t] : 0.f;
    for (int e = t; e < 64 * H; e += 256) {
        int k = e / H, f = e - k * H;
        ws[k * DH + f]     = Wl[e];
        ws[k * DH + H + f] = Wr[e];
    }
    const int o0 = g_off[n], o1 = g_off[n + 1];
    const float inv = g_invdeg[n];
    for (int e = t; e < 64 * CT64; e += 256) {
        int c = e >> 6, k = e & 63;
        float v = 0.f;
        if (c < span) {
            size_t rc = (size_t)(c0 + c);
            v = in[((size_t)n * NC + rc) * DH + k];
            float s = 0.f;
            for (int ee = o0; ee < o1; ee++)
                s += in[((size_t)g_adj[ee] * NC + rc) * DH + H + k];
            v = fmaxf(v + s * inv, 0.f);
        }
        xT[k * PAD64 + c] = v;
    }
    __syncthreads();

    float* yb = out + ((size_t)n * NC + c0) * DH;
    gemm_core<64, CT64, PAD64, false>(xT, ws, bs, yb, span);
}

// ============================================================
// Fused pool: aggregate layer-3 (from g_bufB) on the fly, then
// max+mean pool over 40 nodes, L2-normalize, MLP head -> out[b][c].
// Tile: 50 configs. grid (20, NB).
// ============================================================
__global__ void __launch_bounds__(256)
k_poolf(const float* __restrict__ Wp1, const float* __restrict__ bp1,
        const float* __restrict__ Wp2, const float* __restrict__ bp2,
        float* __restrict__ out) {
    __shared__ float pooled[50 * 64];
    __shared__ float w1s[64 * 32];
    __shared__ float b1s[32];
    __shared__ float w2s[32];
    __shared__ int   s_off[41];
    __shared__ float s_inv[40];
    const int b = blockIdx.y, c0 = blockIdx.x * 50;
    const int t = threadIdx.x;
    for (int e = t; e < 64 * 32; e += 256) w1s[e] = Wp1[e];
    if (t < 32) { b1s[t] = bp1[t]; w2s[t] = Wp2[t]; }
    if (t < 41) s_off[t] = g_off[b * 40 + t];
    if (t < 40) s_inv[t] = g_invdeg[b * 40 + t];
    __syncthreads();
    const float invc = g_invcnt[b];
    for (int idx = t; idx < 50 * 64; idx += 256) {
        int c = idx >> 6, h = idx & 63;
        size_t rc = (size_t)(c0 + c);
        float mx = -3.4e38f, sum = 0.f;
        for (int i = 0; i < 40; i++) {
            int node = b * 40 + i;
            float v = g_bufB[((size_t)node * NC + rc) * DH + h];
            float s = 0.f;
            for (int e = s_off[i]; e < s_off[i + 1]; e++)
                s += g_bufB[((size_t)g_adj[e] * NC + rc) * DH + H + h];
            v = fmaxf(v + s * s_inv[i], 0.f);
            mx = fmaxf(mx, v);
            sum += v;
        }
        pooled[idx] = mx + sum * invc;
    }
    __syncthreads();
    const int w = t >> 5, lane = t & 31;
    const float bp2v = bp2[0];
    for (int c = w; c < 50; c += 8) {
        float v0 = pooled[c * 64 + lane], v1 = pooled[c * 64 + 32 + lane];
        float ss = v0 * v0 + v1 * v1;
        #pragma unroll
        for (int m = 16; m; m >>= 1) ss += __shfl_xor_sync(0xffffffffu, ss, m);
        float inv = rsqrtf(ss);
        float dot = 0.f;
        #pragma unroll
        for (int h = 0; h < 64; h++) dot += pooled[c * 64 + h] * w1s[h * 32 + lane];
        float hj = fmaxf(b1s[lane] + inv * dot, 0.f);
        float o = hj * w2s[lane];
        #pragma unroll
        for (int m = 16; m; m >>= 1) o += __shfl_xor_sync(0xffffffffu, o, m);
        if (lane == 0) out[b * NC + c0 + c] = o + bp2v;
    }
}

// ============================================================
extern "C" void kernel_launch(void* const* d_in, const int* in_sizes, int n_in,
                              void* d_out, int out_size) {
    const float* node_feat   = (const float*)d_in[0];
    const int*   node_opcode = (const int*)d_in[1];
    const float* config_feat = (const float*)d_in[2];
    const int*   edge_index  = (const int*)d_in[3];
    const int*   batch       = (const int*)d_in[4];
    const float* op_emb      = (const float*)d_in[5];
    const float* shape_emb   = (const float*)d_in[6];
    const float* W1  = (const float*)d_in[7];
    const float* b1  = (const float*)d_in[8];
    const float* W2  = (const float*)d_in[9];
    const float* b2  = (const float*)d_in[10];
    const float* Wl0 = (const float*)d_in[11];
    const float* Wr0 = (const float*)d_in[12];
    const float* bg0 = (const float*)d_in[13];
    const float* Wl1 = (const float*)d_in[14];
    const float* Wr1 = (const float*)d_in[15];
    const float* bg1 = (const float*)d_in[16];
    const float* Wl2 = (const float*)d_in[17];
    const float* Wr2 = (const float*)d_in[18];
    const float* bg2 = (const float*)d_in[19];
    const float* Wp1 = (const float*)d_in[20];
    const float* bp1 = (const float*)d_in[21];
    const float* Wp2 = (const float*)d_in[22];
    const float* bp2 = (const float*)d_in[23];
    float* out = (float*)d_out;

    const int SM_MLP  = (2 * DH + CF * DH + CF * PADW + DH * PADW + DH * DH) * 4; // ~159 KB
    const int SM_G128 = (128 * PAD64 + 128 * DH + DH) * 4;                         // ~101 KB (x2 CTAs)
    const int SM_G64  = (64 * PAD64 + 64 * DH + DH) * 4;                           // ~49.5 KB (x2 CTAs)
    cudaFuncSetAttribute(k_mlp,             cudaFuncAttributeMaxDynamicSharedMemorySize, SM_MLP);
    cudaFuncSetAttribute(k_sageG128,        cudaFuncAttributeMaxDynamicSharedMemorySize, SM_G128);
    cudaFuncSetAttribute(k_sageG64f<true>,  cudaFuncAttributeMaxDynamicSharedMemorySize, SM_G64);
    cudaFuncSetAttribute(k_sageG64f<false>, cudaFuncAttributeMaxDynamicSharedMemorySize, SM_G64);

    k_prep<<<1, 512>>>(edge_index, batch);
    k_base<<<NN, 128>>>(node_feat, node_opcode, op_emb, shape_emb, W1, b1);

    dim3 gmlp(8, NN);
    k_mlp<<<gmlp, 512, SM_MLP>>>(config_feat, batch, W1, W2, b2);

    dim3 g64(16, NN);
    k_sageG128<<<g64, 256, SM_G128>>>(Wl0, Wr0, bg0);       // A -> B (proj L0)
    k_sageG64f<true><<<g64, 256, SM_G64>>>(Wl1, Wr1, bg1);  // agg B -> proj -> A
    k_sageG64f<false><<<g64, 256, SM_G64>>>(Wl2, Wr2, bg2); // agg A -> proj -> B

    dim3 gpool(20, NB);
    k_poolf<<<gpool, 256>>>(Wp1, bp1, Wp2, bp2, out);       // agg B -> pool -> head
}

// round 8
// speedup vs baseline: 1.2611x; 1.2611x over previous
#include <cuda_runtime.h>

#define NN 400
#define NC 1000
#define NB 10
#define NE 800
#define XND 121   // 85 cont + 4 shape emb + 32 op emb
#define CF 24
#define DH 128    // 2H
#define H 64
#define CT 128    // configs per tile (sageG64)
#define PADW 132  // padded smem row stride for 128-wide tiles
#define CT64 64   // configs per tile (sageG128, mlp2)
#define PAD64 68  // padded smem row stride for 64-wide tiles

typedef unsigned long long ull_t;

// ---- scratch (module-load allocated, no cudaMalloc) ----
__device__ float g_bufA[(size_t)NN * NC * DH];  // 204.8 MB
__device__ float g_bufB[(size_t)NN * NC * DH];  // 204.8 MB
__device__ float g_base[NN * DH];
__device__ float g_proj[(size_t)NB * NC * DH];  // 5.12 MB
__device__ int   g_adj[NE];
__device__ int   g_off[NN + 1];
__device__ float g_invdeg[NN];
__device__ float g_invcnt[NB];

// ---- packed f32x2 helpers ----
__device__ __forceinline__ ull_t pk2(float x) {
    ull_t r; asm("mov.b64 %0, {%1, %1};" : "=l"(r) : "f"(x)); return r;
}
__device__ __forceinline__ ull_t fma2(ull_t a, ull_t b, ull_t c) {
    ull_t d; asm("fma.rn.f32x2 %0, %1, %2, %3;" : "=l"(d) : "l"(a), "l"(b), "l"(c)); return d;
}
__device__ __forceinline__ void upk(ull_t a, float& lo, float& hi) {
    asm("mov.b64 {%0, %1}, %2;" : "=f"(lo), "=f"(hi) : "l"(a));
}

// ============================================================
// Register-tiled GEMM core: 128 features x CW configs.
// REQUIRES blockDim == 32*(CW/8). Thread tile: 4f x 8c.
// ============================================================
template<int D, int CW, int PAD, bool RELU>
__device__ __forceinline__ void gemm_core(const float* __restrict__ xT,
                                          const float* __restrict__ ws,
                                          const float* __restrict__ bs128,
                                          float* __restrict__ outg, int span) {
    const int t  = threadIdx.x;
    const int f0 = (t & 31) * 4;
    const int c0 = (t >> 5) * 8;

    ull_t acc[4][4];
    {
        float4 bv = *(const float4*)(bs128 + f0);
        ull_t b0 = pk2(bv.x), b1 = pk2(bv.y), b2_ = pk2(bv.z), b3 = pk2(bv.w);
        #pragma unroll
        for (int p = 0; p < 4; p++) { acc[0][p] = b0; acc[1][p] = b1; acc[2][p] = b2_; acc[3][p] = b3; }
    }

    #pragma unroll 4
    for (int k = 0; k < D; k++) {
        float4 wv = *(const float4*)(ws + k * DH + f0);
        ull_t w0 = pk2(wv.x), w1 = pk2(wv.y), w2 = pk2(wv.z), w3 = pk2(wv.w);
        const ulonglong2* xr = (const ulonglong2*)(xT + k * PAD + c0);
        ulonglong2 xA = xr[0], xB = xr[1];
        acc[0][0] = fma2(xA.x, w0, acc[0][0]);
        acc[1][0] = fma2(xA.x, w1, acc[1][0]);
        acc[2][0] = fma2(xA.x, w2, acc[2][0]);
        acc[3][0] = fma2(xA.x, w3, acc[3][0]);
        acc[0][1] = fma2(xA.y, w0, acc[0][1]);
        acc[1][1] = fma2(xA.y, w1, acc[1][1]);
        acc[2][1] = fma2(xA.y, w2, acc[2][1]);
        acc[3][1] = fma2(xA.y, w3, acc[3][1]);
        acc[0][2] = fma2(xB.x, w0, acc[0][2]);
        acc[1][2] = fma2(xB.x, w1, acc[1][2]);
        acc[2][2] = fma2(xB.x, w2, acc[2][2]);
        acc[3][2] = fma2(xB.x, w3, acc[3][2]);
        acc[0][3] = fma2(xB.y, w0, acc[0][3]);
        acc[1][3] = fma2(xB.y, w1, acc[1][3]);
        acc[2][3] = fma2(xB.y, w2, acc[2][3]);
        acc[3][3] = fma2(xB.y, w3, acc[3][3]);
    }

    #pragma unroll
    for (int p = 0; p < 4; p++) {
        int c = c0 + 2 * p;
        float lo0, hi0, lo1, hi1, lo2, hi2, lo3, hi3;
        upk(acc[0][p], lo0, hi0); upk(acc[1][p], lo1, hi1);
        upk(acc[2][p], lo2, hi2); upk(acc[3][p], lo3, hi3);
        if (RELU) {
            lo0 = fmaxf(lo0, 0.f); hi0 = fmaxf(hi0, 0.f);
            lo1 = fmaxf(lo1, 0.f); hi1 = fmaxf(hi1, 0.f);
            lo2 = fmaxf(lo2, 0.f); hi2 = fmaxf(hi2, 0.f);
            lo3 = fmaxf(lo3, 0.f); hi3 = fmaxf(hi3, 0.f);
        }
        if (c < span)     *(float4*)(outg + (size_t)c * DH + f0)       = make_float4(lo0, lo1, lo2, lo3);
        if (c + 1 < span) *(float4*)(outg + (size_t)(c + 1) * DH + f0) = make_float4(hi0, hi1, hi2, hi3);
    }
}

// ============================================================
// Setup: CSR by dst, degrees, per-graph node counts. One block.
// ============================================================
__global__ void k_prep(const int* __restrict__ ei, const int* __restrict__ batch) {
    __shared__ int cnt[NN];
    __shared__ int off[NN + 1];
    __shared__ int cur[NN];
    __shared__ int bc[NB];
    int t = threadIdx.x;
    for (int i = t; i < NN; i += blockDim.x) cnt[i] = 0;
    if (t < NB) bc[t] = 0;
    __syncthreads();
    for (int e = t; e < NE; e += blockDim.x) atomicAdd(&cnt[ei[NE + e]], 1);
    for (int i = t; i < NN; i += blockDim.x) atomicAdd(&bc[batch[i]], 1);
    __syncthreads();
    if (t == 0) {
        int s = 0;
        for (int i = 0; i < NN; i++) { off[i] = s; s += cnt[i]; }
        off[NN] = s;
    }
    __syncthreads();
    for (int i = t; i < NN; i += blockDim.x) {
        cur[i] = off[i];
        g_off[i] = off[i];
        g_invdeg[i] = 1.f / fmaxf((float)cnt[i], 1.f);
    }
    if (t == 0) g_off[NN] = off[NN];
    if (t < NB) g_invcnt[t] = 1.f / fmaxf((float)bc[t], 1.f);
    __syncthreads();
    for (int e = t; e < NE; e += blockDim.x) {
        int d = ei[NE + e];
        int p = atomicAdd(&cur[d], 1);
        g_adj[p] = ei[e];
    }
}

// ============================================================
// Per-node config-invariant part of layer 1:
// base[n][f] = b1[f] + xn[n] @ W1[0:121]
// ============================================================
__global__ void k_base(const float* __restrict__ node_feat, const int* __restrict__ opcode,
                       const float* __restrict__ op_emb, const float* __restrict__ shape_emb,
                       const float* __restrict__ W1, const float* __restrict__ b1) {
    __shared__ float xns[XND];
    int n = blockIdx.x, t = threadIdx.x;
    if (t < XND) {
        float v;
        if (t < 85) v = node_feat[n * 86 + t];
        else if (t < 89) { int st = (int)node_feat[n * 86 + 85]; v = shape_emb[st * 4 + (t - 85)]; }
        else v = op_emb[opcode[n] * 32 + (t - 89)];
        xns[t] = v;
    }
    __syncthreads();
    float acc = b1[t];
    #pragma unroll 11
    for (int k = 0; k < XND; k++) acc += xns[k] * W1[k * DH + t];
    g_base[n * DH + t] = acc;
}

// ============================================================
// Per-graph config projection: proj[b][c][f] = cfg[b,c] @ W1[121:145]
// (shared by all 40 nodes of graph b). 40 rows per block, grid=250.
// ============================================================
__global__ void __launch_bounds__(256)
k_proj(const float* __restrict__ cfgf, const float* __restrict__ W1) {
    __shared__ float w1t[CF * DH];   // 12 KB
    __shared__ float cfgs[40 * CF];  // 3.75 KB
    const int r0 = blockIdx.x * 40;  // row = b*NC + c, 10000 rows total
    const int t = threadIdx.x;
    for (int e = t; e < CF * DH; e += 256) w1t[e] = W1[XND * DH + e];
    for (int e = t; e < 40 * CF; e += 256) cfgs[e] = cfgf[(size_t)r0 * CF + e];
    __syncthreads();
    const int f = t & 127, rh = t >> 7;  // rh in {0,1}
    for (int rr = rh; rr < 40; rr += 2) {
        float acc = 0.f;
        #pragma unroll
        for (int j = 0; j < CF; j++) acc += cfgs[rr * CF + j] * w1t[j * DH + f];
        g_proj[(size_t)(r0 + rr) * DH + f] = acc;
    }
}

// ============================================================
// MLP stage-2: x1 = relu(base[n] + proj[b][c]) (fill from gmem),
// x2 = relu(x1 @ W2 + b2) -> g_bufA.  256 thr, 64c tile, 2 CTAs/SM.
// ============================================================
__global__ void __launch_bounds__(256, 2)
k_mlp2(const int* __restrict__ batch, const float* __restrict__ W2, const float* __restrict__ b2) {
    extern __shared__ float sm[];
    float* sb  = sm;                  // 128 (base)
    float* b2s = sm + DH;             // 128
    float* x1T = b2s + DH;            // 128*PAD64
    float* w2s = x1T + 128 * PAD64;   // 128*128

    const int n = blockIdx.y, c0 = blockIdx.x * CT64;
    const int span = min(CT64, NC - c0);
    const int t = threadIdx.x;

    if (t < DH) { sb[t] = g_base[n * DH + t]; b2s[t] = b2[t]; }
    for (int e = t; e < DH * DH; e += 256) w2s[e] = W2[e];
    const int bn = batch[n];
    const float* pr = g_proj + ((size_t)bn * NC + c0) * DH;
    for (int e = t; e < 128 * CT64; e += 256) {
        int c = e >> 7, k = e & 127;
        float v = 0.f;
        if (c < span) v = fmaxf(sb[k] + pr[(size_t)c * DH + k], 0.f);
        x1T[k * PAD64 + c] = v;
    }
    __syncthreads();

    float* outg = g_bufA + ((size_t)n * NC + c0) * DH;
    gemm_core<128, CT64, PAD64, true>(x1T, w2s, b2s, outg, span);
}

// ============================================================
// SAGE projection layer 0 (D=128 input): 256 threads, 64c tile,
// 2 CTAs/SM. Reads g_bufA, writes g_bufB = (Wl·x+bg | Wr·x).
// ============================================================
__global__ void __launch_bounds__(256, 2)
k_sageG128(const float* __restrict__ Wl, const float* __restrict__ Wr, const float* __restrict__ bg) {
    extern __shared__ float sm[];
    float* xT = sm;                  // 128*PAD64
    float* ws = xT + 128 * PAD64;    // 128*128 (Wl | Wr interleaved on f)
    float* bs = ws + 128 * DH;       // 128 (bg | zeros)
    const int n = blockIdx.y, c0 = blockIdx.x * CT64;
    const int span = min(CT64, NC - c0);
    const int t = threadIdx.x;

    if (t < DH) bs[t] = (t < H) ? bg[t] : 0.f;
    for (int e = t; e < 128 * H; e += 256) {
        int k = e / H, f = e - k * H;
        ws[k * DH + f]     = Wl[e];
        ws[k * DH + H + f] = Wr[e];
    }
    const float* xb = g_bufA + ((size_t)n * NC + c0) * 128;
    for (int e = t; e < 128 * CT64; e += 256) {
        int c = e >> 7, k = e & 127;
        xT[k * PAD64 + c] = (c < span) ? xb[e] : 0.f;
    }
    __syncthreads();

    float* yb = g_bufB + ((size_t)n * NC + c0) * DH;
    gemm_core<128, CT64, PAD64, false>(xT, ws, bs, yb, span);
}

// ============================================================
// SAGE projection (D=64 input): 256 threads, 128c tile (4f x 16c),
// 2 CTAs/SM. Reads g_bufA[...][64], writes g_bufB.
// ============================================================
__global__ void __launch_bounds__(256, 2)
k_sageG64(const float* __restrict__ Wl, const float* __restrict__ Wr, const float* __restrict__ bg) {
    extern __shared__ float sm[];
    float* xT = sm;                // 64*PADW
    float* ws = xT + 64 * PADW;    // 64*128
    float* bs = ws + 64 * DH;      // 128
    const int n = blockIdx.y, c0 = blockIdx.x * CT;
    const int span = min(CT, NC - c0);
    const int t = threadIdx.x;

    if (t < DH) bs[t] = (t < H) ? bg[t] : 0.f;
    for (int e = t; e < 64 * H; e += 256) {
        int k = e / H, f = e - k * H;
        ws[k * DH + f]     = Wl[e];
        ws[k * DH + H + f] = Wr[e];
    }
    const float* xb = g_bufA + ((size_t)n * NC + c0) * 64;
    for (int e = t; e < 64 * CT; e += 256) {
        int c = e >> 6, k = e & 63;
        xT[k * PADW + c] = (c < span) ? xb[e] : 0.f;
    }
    __syncthreads();

    // 4f x 16c register tile (8 warps cover 128 configs)
    const int f0 = (t & 31) * 4;
    const int c0t = (t >> 5) * 16;
    ull_t acc[4][8];
    {
        float4 bv = *(const float4*)(bs + f0);
        ull_t b0 = pk2(bv.x), b1 = pk2(bv.y), b2_ = pk2(bv.z), b3 = pk2(bv.w);
        #pragma unroll
        for (int p = 0; p < 8; p++) { acc[0][p] = b0; acc[1][p] = b1; acc[2][p] = b2_; acc[3][p] = b3; }
    }
    #pragma unroll 4
    for (int k = 0; k < 64; k++) {
        float4 wv = *(const float4*)(ws + k * DH + f0);
        ull_t w0 = pk2(wv.x), w1 = pk2(wv.y), w2 = pk2(wv.z), w3 = pk2(wv.w);
        const ulonglong2* xr = (const ulonglong2*)(xT + k * PADW + c0t);
        #pragma unroll
        for (int q = 0; q < 4; q++) {
            ulonglong2 xv = xr[q];
            acc[0][2*q]   = fma2(xv.x, w0, acc[0][2*q]);
            acc[1][2*q]   = fma2(xv.x, w1, acc[1][2*q]);
            acc[2][2*q]   = fma2(xv.x, w2, acc[2][2*q]);
            acc[3][2*q]   = fma2(xv.x, w3, acc[3][2*q]);
            acc[0][2*q+1] = fma2(xv.y, w0, acc[0][2*q+1]);
            acc[1][2*q+1] = fma2(xv.y, w1, acc[1][2*q+1]);
            acc[2][2*q+1] = fma2(xv.y, w2, acc[2][2*q+1]);
            acc[3][2*q+1] = fma2(xv.y, w3, acc[3][2*q+1]);
        }
    }
    float* yb = g_bufB + ((size_t)n * NC + c0) * DH;
    #pragma unroll
    for (int p = 0; p < 8; p++) {
        int c = c0t + 2 * p;
        float lo0, hi0, lo1, hi1, lo2, hi2, lo3, hi3;
        upk(acc[0][p], lo0, hi0); upk(acc[1][p], lo1, hi1);
        upk(acc[2][p], lo2, hi2); upk(acc[3][p], lo3, hi3);
        if (c < span)     *(float4*)(yb + (size_t)c * DH + f0)       = make_float4(lo0, lo1, lo2, lo3);
        if (c + 1 < span) *(float4*)(yb + (size_t)(c + 1) * DH + f0) = make_float4(hi0, hi1, hi2, hi3);
    }
}

// ============================================================
// SAGE aggregate: x' = relu(y[dst][:,0:64] + (sum_{src} y[src][:,64:128])/deg)
// Reads g_bufB, writes g_bufA [n][c][64].
// ============================================================
__global__ void k_sageA() {
    const int n = blockIdx.y, c0 = blockIdx.x * CT;
    const int span = min(CT, NC - c0);
    const int o0 = g_off[n], o1 = g_off[n + 1];
    const float inv = g_invdeg[n];
    const int tot = span * H;
    const float* yb = g_bufB + ((size_t)n * NC + c0) * DH;
    float* xb = g_bufA + ((size_t)n * NC + c0) * H;
    for (int idx = threadIdx.x; idx < tot; idx += 256) {
        int c = idx >> 6, h = idx & 63;
        float s = 0.f;
        for (int e = o0; e < o1; e++) {
            int src = g_adj[e];
            s += g_bufB[((size_t)src * NC + c0 + c) * DH + H + h];
        }
        float v = yb[(size_t)c * DH + h] + s * inv;
        xb[idx] = fmaxf(v, 0.f);
    }
}

// ============================================================
// Pool (max + mean over 40 nodes), L2-normalize, MLP head -> out[b][c]
// ============================================================
__global__ void __launch_bounds__(256)
k_pool(const float* __restrict__ Wp1, const float* __restrict__ bp1,
       const float* __restrict__ Wp2, const float* __restrict__ bp2,
       float* __restrict__ out) {
    __shared__ float pooled[100 * 64];
    __shared__ float w1s[64 * 32];
    __shared__ float b1s[32];
    __shared__ float w2s[32];
    const int b = blockIdx.y, c0 = blockIdx.x * 100;
    const int t = threadIdx.x;
    for (int e = t; e < 64 * 32; e += 256) w1s[e] = Wp1[e];
    if (t < 32) { b1s[t] = bp1[t]; w2s[t] = Wp2[t]; }
    const float invc = g_invcnt[b];
    const float* xb = g_bufA + ((size_t)(b * 40) * NC + c0) * H;
    for (int idx = t; idx < 100 * 64; idx += 256) {
        int c = idx >> 6, h = idx & 63;
        float mx = -3.4e38f, sm_ = 0.f;
        for (int i = 0; i < 40; i++) {
            float v = xb[((size_t)i * NC + c) * H + h];
            mx = fmaxf(mx, v);
            sm_ += v;
        }
        pooled[idx] = mx + sm_ * invc;
    }
    __syncthreads();
    const int w = t >> 5, lane = t & 31;
    const float bp2v = bp2[0];
    for (int c = w; c < 100; c += 8) {
        float v0 = pooled[c * 64 + lane], v1 = pooled[c * 64 + 32 + lane];
        float ss = v0 * v0 + v1 * v1;
        #pragma unroll
        for (int m = 16; m; m >>= 1) ss += __shfl_xor_sync(0xffffffffu, ss, m);
        float inv = rsqrtf(ss);
        float dot = 0.f;
        #pragma unroll
        for (int h = 0; h < 64; h++) dot += pooled[c * 64 + h] * w1s[h * 32 + lane];
        float hj = fmaxf(b1s[lane] + inv * dot, 0.f);
        float o = hj * w2s[lane];
        #pragma unroll
        for (int m = 16; m; m >>= 1) o += __shfl_xor_sync(0xffffffffu, o, m);
        if (lane == 0) out[b * NC + c0 + c] = o + bp2v;
    }
}

// ============================================================
extern "C" void kernel_launch(void* const* d_in, const int* in_sizes, int n_in,
                              void* d_out, int out_size) {
    const float* node_feat   = (const float*)d_in[0];
    const int*   node_opcode = (const int*)d_in[1];
    const float* config_feat = (const float*)d_in[2];
    const int*   edge_index  = (const int*)d_in[3];
    const int*   batch       = (const int*)d_in[4];
    const float* op_emb      = (const float*)d_in[5];
    const float* shape_emb   = (const float*)d_in[6];
    const float* W1  = (const float*)d_in[7];
    const float* b1  = (const float*)d_in[8];
    const float* W2  = (const float*)d_in[9];
    const float* b2  = (const float*)d_in[10];
    const float* Wl0 = (const float*)d_in[11];
    const float* Wr0 = (const float*)d_in[12];
    const float* bg0 = (const float*)d_in[13];
    const float* Wl1 = (const float*)d_in[14];
    const float* Wr1 = (const float*)d_in[15];
    const float* bg1 = (const float*)d_in[16];
    const float* Wl2 = (const float*)d_in[17];
    const float* Wr2 = (const float*)d_in[18];
    const float* bg2 = (const float*)d_in[19];
    const float* Wp1 = (const float*)d_in[20];
    const float* bp1 = (const float*)d_in[21];
    const float* Wp2 = (const float*)d_in[22];
    const float* bp2 = (const float*)d_in[23];
    float* out = (float*)d_out;

    const int SM_MLP2 = (2 * DH + 128 * PAD64 + DH * DH) * 4;        // ~101.4 KB (x2 CTAs)
    const int SM_G128 = (128 * PAD64 + 128 * DH + DH) * 4;           // ~101.4 KB (x2 CTAs)
    const int SM_G64  = (64 * PADW + 64 * DH + DH) * 4;              // ~67 KB (x2 CTAs)
    cudaFuncSetAttribute(k_mlp2,     cudaFuncAttributeMaxDynamicSharedMemorySize, SM_MLP2);
    cudaFuncSetAttribute(k_sageG128, cudaFuncAttributeMaxDynamicSharedMemorySize, SM_G128);
    cudaFuncSetAttribute(k_sageG64,  cudaFuncAttributeMaxDynamicSharedMemorySize, SM_G64);

    k_prep<<<1, 512>>>(edge_index, batch);
    k_base<<<NN, 128>>>(node_feat, node_opcode, op_emb, shape_emb, W1, b1);
    k_proj<<<250, 256>>>(config_feat, W1);

    dim3 g64t(16, NN);
    k_mlp2<<<g64t, 256, SM_MLP2>>>(batch, W2, b2);          // -> A (post-MLP)
    k_sageG128<<<g64t, 256, SM_G128>>>(Wl0, Wr0, bg0);      // A -> B (proj L0)

    dim3 g128t(8, NN);
    k_sageA<<<g128t, 256>>>();                              // B -> A (agg L0)
    k_sageG64<<<g128t, 256, SM_G64>>>(Wl1, Wr1, bg1);       // A -> B (proj L1)
    k_sageA<<<g128t, 256>>>();                              // B -> A (agg L1)
    k_sageG64<<<g128t, 256, SM_G64>>>(Wl2, Wr2, bg2);       // A -> B (proj L2)
    k_sageA<<<g128t, 256>>>();                              // B -> A (agg L2)

    dim3 gpool(10, NB);
    k_pool<<<gpool, 256>>>(Wp1, bp1, Wp2, bp2, out);
}